// round 13
// baseline (speedup 1.0000x reference)
#include <cuda_runtime.h>
#include <cuda_bf16.h>
#include <cstdint>

// Problem constants
#define BATCH   8
#define NW      64
#define NTOK    64
#define DIM     512
#define HEADS   16
#define HD      32
#define C3      1536
#define MROWS   (BATCH*NW*NTOK)   // 32768
#define LN100   4.605170185988092f

// Scratch (allocation-free rule: __device__ globals)
__device__ float g_qkv[(long)MROWS * C3];     // 192 MB (GEMM1 out, fp32 natural)
__device__ float g_att[(long)MROWS * DIM];    // 64 MB  (attn out, A-frag layout)
__device__ float g_xc [(long)MROWS * DIM];    // 64 MB  (x, A-frag layout)
__device__ float g_wqc[(long)C3 * DIM];       // 3 MB   (qkv W, B-frag layout)
__device__ float g_wpc[(long)DIM * DIM];      // 1 MB   (proj W, B-frag layout)
__device__ float g_ropeC[64 * 16];            // RoPE cos table [row][p]
__device__ float g_ropeS[64 * 16];            // RoPE sin table [row][p]

__device__ __forceinline__ unsigned f2tf32(float x) {
    unsigned u;
    asm("cvt.rna.tf32.f32 %0, %1;" : "=r"(u) : "f"(x));
    return u;
}
__device__ __forceinline__ void mma_tf32(float c[4], const unsigned a[4], const unsigned b[2]) {
    asm volatile(
        "mma.sync.aligned.m16n8k8.row.col.f32.tf32.tf32.f32 "
        "{%0,%1,%2,%3}, {%4,%5,%6,%7}, {%8,%9}, {%0,%1,%2,%3};"
        : "+f"(c[0]), "+f"(c[1]), "+f"(c[2]), "+f"(c[3])
        : "r"(a[0]), "r"(a[1]), "r"(a[2]), "r"(a[3]), "r"(b[0]), "r"(b[1]));
}
__device__ __forceinline__ int perm8(int kk) { return ((kk & 3) << 1) | (kk >> 2); }

__device__ __forceinline__ void cp_async16(uint32_t saddr, const void* g) {
    asm volatile("cp.async.cg.shared.global [%0], [%1], 16;" :: "r"(saddr), "l"(g));
}
__device__ __forceinline__ void cp_commit() { asm volatile("cp.async.commit_group;"); }
template<int Nw>
__device__ __forceinline__ void cp_wait() { asm volatile("cp.async.wait_group %0;" :: "n"(Nw)); }

// A-fragment layout index for element (m, k), K=512 fixed.
__device__ __forceinline__ long a_frag_idx(int m, int k) {
    const int mtile = m >> 7, mtg = (m >> 4) & 7, g = m & 7, hi = (m >> 3) & 1;
    const int ktile = k >> 5, ks = (k >> 3) & 3, t4 = k & 3, hk = (k >> 2) & 1;
    return ((long)(mtile * 16 + ktile)) * 4096 + (mtg * 4 + ks) * 128 + (g * 4 + t4) * 4 + hi + 2 * hk;
}

// ---------------------------------------------------------------------------
// RoPE table init (bitwise-identical sincosf values).
// ---------------------------------------------------------------------------
__global__ void rope_init()
{
    const int tid = threadIdx.x;            // 0..1023
    const int r = tid >> 4, p = tid & 15;
    const float inv_tab[8] = {
        1.0f, 0.31622776601683794f, 0.1f, 0.03162277660168379f,
        0.01f, 0.0031622776601683794f, 0.001f, 0.00031622776601683794f };
    const int ih = r >> 3, iw = r & 7;
    const float pos = (p < 8) ? (float)ih : (float)iw;
    const float f = pos * inv_tab[p & 7];
    float sf, cf;
    sincosf(f, &sf, &cf);
    g_ropeC[r * 16 + p] = cf;
    g_ropeS[r * 16 + p] = sf;
}

// ---------------------------------------------------------------------------
// Pre-pass A: scatter x into A-fragment layout, tf32.
// ---------------------------------------------------------------------------
__global__ __launch_bounds__(256) void prepA(
    const float* __restrict__ in, float* __restrict__ out, int nChunks)
{
    const int tid = blockIdx.x * 256 + threadIdx.x;
    if (tid >= nChunks) return;
    const int lane = tid & 31;
    const int t2   = tid >> 5;
    const int ks   = t2 & 3;
    const int mtg  = (t2 >> 2) & 7;
    const int kt   = (t2 >> 5) & 15;
    const int mt   = t2 >> 9;
    const int g = lane >> 2, t4 = lane & 3;
    const long r0 = mt * 128 + mtg * 16 + g;
    const int  k0 = kt * 32 + ks * 8 + t4;
    uint4 v;
    v.x = f2tf32(in[r0 * 512 + k0]);
    v.y = f2tf32(in[(r0 + 8) * 512 + k0]);
    v.z = f2tf32(in[r0 * 512 + k0 + 4]);
    v.w = f2tf32(in[(r0 + 8) * 512 + k0 + 4]);
    *(uint4*)(out + (long)tid * 4) = v;
}

// ---------------------------------------------------------------------------
// Pre-pass B: scatter W into B-fragment layout, tf32.
// ---------------------------------------------------------------------------
__global__ __launch_bounds__(256) void prepB(
    const float* __restrict__ in, float* __restrict__ out, int nChunks)
{
    const int tid = blockIdx.x * 256 + threadIdx.x;
    if (tid >= nChunks) return;
    const int lane = tid & 31;
    const int t2   = tid >> 5;
    const int kp   = t2 & 1;
    const int ntg  = (t2 >> 1) & 15;
    const int kt   = (t2 >> 5) & 15;
    const int nt   = t2 >> 9;
    const int g = lane >> 2, t4 = lane & 3;
    const long n  = nt * 128 + ntg * 8 + g;
    const int  k0 = kt * 32 + kp * 16 + t4;
    uint4 v;
    v.x = f2tf32(in[n * 512 + k0]);
    v.y = f2tf32(in[n * 512 + k0 + 4]);
    v.z = f2tf32(in[n * 512 + k0 + 8]);
    v.w = f2tf32(in[n * 512 + k0 + 12]);
    *(uint4*)(out + (long)tid * 4) = v;
}

// ---------------------------------------------------------------------------
// TF32 mma.sync GEMM on fragment-layout operands.
// CTA 128x128, BK=32, 256 threads = 8 warps (2M x 4N), warp tile 64x32.
// Fragment loads contiguous LDS.128; cp.async 3-stage (R9 loop order).
// Per-output k-accumulation order identical to R9 -> bitwise-equal results.
// ---------------------------------------------------------------------------
template<int N, int MODE>
__global__ __launch_bounds__(256, 2) void mma_gemm(
    const float* __restrict__ A, const float* __restrict__ W,
    const float* __restrict__ b0, const float* __restrict__ b1,
    float* __restrict__ C)
{
    constexpr int NT = 16;
    extern __shared__ unsigned sm[];

    const int t    = threadIdx.x;
    const int warp = t >> 5;
    const int lane = t & 31;
    const int g    = lane >> 2;
    const int t4   = lane & 3;
    const int wm   = warp >> 2;               // 0..1 (M)
    const int wn   = warp & 3;                // 0..3 (N)

    const int rowBase = blockIdx.y * 128;
    const int colBase = blockIdx.x * 128;

    const float* Abase = A + (long)blockIdx.y * 16 * 4096;
    const float* Wbase = W + (long)blockIdx.x * 16 * 4096;

    const uint32_t smBase = (uint32_t)__cvta_generic_to_shared(sm);

    auto issue = [&](int s, int i) {
        const float* Ag = Abase + (long)i * 4096;
        const float* Wg = Wbase + (long)i * 4096;
        #pragma unroll
        for (int p = 0; p < 8; ++p) {
            const int c = t + p * 256;        // 0..2047
            const float* src = (c < 1024) ? (Ag + c * 4) : (Wg + (c - 1024) * 4);
            cp_async16(smBase + (uint32_t)(s * 8192 + c * 4) * 4u, src);
        }
        cp_commit();
    };

    float acc[4][4][4] = {};   // [mt][nt][4], warp tile 64x32

    issue(0, 0);
    issue(1, 1);

    for (int i = 0; i < NT; ++i) {
        cp_wait<1>();
        __syncthreads();

        const unsigned* as = sm + (i % 3) * 8192;
        const unsigned* bs = as + 4096;

        #pragma unroll
        for (int kp = 0; kp < 2; ++kp) {
            uint4 bq[4];
            #pragma unroll
            for (int nt = 0; nt < 4; ++nt)
                bq[nt] = *(const uint4*)(bs + (((wn * 4 + nt) * 2 + kp) * 32 + lane) * 4);
            #pragma unroll
            for (int s2 = 0; s2 < 2; ++s2) {
                const int ks = kp * 2 + s2;
                unsigned af[4][4];
                #pragma unroll
                for (int mt = 0; mt < 4; ++mt) {
                    uint4 aq = *(const uint4*)(as + (((wm * 4 + mt) * 4 + ks) * 32 + lane) * 4);
                    af[mt][0] = aq.x; af[mt][1] = aq.y; af[mt][2] = aq.z; af[mt][3] = aq.w;
                }
                #pragma unroll
                for (int mt = 0; mt < 4; ++mt)
                    #pragma unroll
                    for (int nt = 0; nt < 4; ++nt) {
                        unsigned bf[2];
                        bf[0] = s2 ? bq[nt].z : bq[nt].x;
                        bf[1] = s2 ? bq[nt].w : bq[nt].y;
                        mma_tf32(acc[mt][nt], af[mt], bf);
                    }
            }
        }

        if (i + 2 < NT) issue((i + 2) % 3, i + 2);
        else cp_commit();
    }

    // epilogue with bias (natural row-major output)
    #pragma unroll
    for (int mt = 0; mt < 4; ++mt) {
        #pragma unroll
        for (int nt = 0; nt < 4; ++nt) {
            const int row0 = rowBase + wm*64 + mt*16 + g;
            const int col0 = colBase + wn*32 + nt*8 + t4*2;
            float bias0, bias1;
            if (MODE == 0) {
                bias0 = (col0 < 512) ? b0[col0] : ((col0 < 1024) ? 0.0f : b1[col0 - 1024]);
                const int c1 = col0 + 1;
                bias1 = (c1 < 512) ? b0[c1] : ((c1 < 1024) ? 0.0f : b1[c1 - 1024]);
            } else {
                bias0 = b0[col0];
                bias1 = b0[col0 + 1];
            }
            C[(long)row0 * N + col0    ] = acc[mt][nt][0] + bias0;
            C[(long)row0 * N + col0 + 1] = acc[mt][nt][1] + bias1;
            C[(long)(row0+8) * N + col0    ] = acc[mt][nt][2] + bias0;
            C[(long)(row0+8) * N + col0 + 1] = acc[mt][nt][3] + bias1;
        }
    }
}

// ---------------------------------------------------------------------------
// Per-window cosine attention with axial RoPE — tensor-core (3xTF32 = ~fp32).
// RoPE sin/cos from precomputed table. Output in A-fragment layout for GEMM2.
// ---------------------------------------------------------------------------
__global__ __launch_bounds__(256, 2) void attn_kernel(
    const float* __restrict__ logit_scale, float* __restrict__ out)
{
    __shared__ float sq [64][40];
    __shared__ float sk [64][40];
    __shared__ float svT[32][72];
    __shared__ float sp [64][72];

    const int w = blockIdx.x, h = blockIdx.y, b = blockIdx.z;
    const int t    = threadIdx.x;
    const int warp = t >> 5;
    const int lane = t & 31;
    const int g    = lane >> 2;
    const int t4   = lane & 3;
    const int wm   = warp >> 2;
    const int wn   = warp & 3;

    const long rowm = (long)(b * NW + w) * NTOK;
    const float* qp = g_qkv + rowm * C3 + h * HD;
    const float* kp = qp + 512;
    const float* vp = qp + 1024;

    #pragma unroll
    for (int it = 0; it < 2; ++it) {
        int idx = t + it * 256;
        int r = idx >> 3, c = (idx & 7) * 4;
        *(float4*)&sq[r][c] = *(const float4*)(qp + (long)r * C3 + c);
        *(float4*)&sk[r][c] = *(const float4*)(kp + (long)r * C3 + c);
    }
    {
        const int r  = t & 63;
        const int pr = (r >> 3) * 8 + perm8(r & 7);
        #pragma unroll
        for (int it = 0; it < 2; ++it) {
            int c = ((t >> 6) * 2 + it) * 4;
            float4 v = *(const float4*)(vp + (long)r * C3 + c);
            svT[c+0][pr] = v.x; svT[c+1][pr] = v.y;
            svT[c+2][pr] = v.z; svT[c+3][pr] = v.w;
        }
    }
    __syncthreads();

    if (t < 128) {
        const int r = t & 63;
        float* row = (t < 64) ? &sq[r][0] : &sk[r][0];
        float x[32];
        #pragma unroll
        for (int c4 = 0; c4 < 8; ++c4) *(float4*)&x[c4*4] = *(float4*)&row[c4*4];

        float ss = 0.f;
        #pragma unroll
        for (int d = 0; d < 32; ++d) ss += x[d] * x[d];
        float scale = 1.0f / fmaxf(sqrtf(ss), 1e-12f);
        if (t < 64)
            scale *= expf(fmaxf(logit_scale[h], LN100)) * 0.17677669529663687f;

        float cf[16], sf[16];
        #pragma unroll
        for (int q4 = 0; q4 < 4; ++q4) {
            *(float4*)&cf[q4*4] = *(const float4*)&g_ropeC[r*16 + q4*4];
            *(float4*)&sf[q4*4] = *(const float4*)&g_ropeS[r*16 + q4*4];
        }

        float y[32];
        #pragma unroll
        for (int p = 0; p < 16; ++p) {
            const int d = 2 * p;
            const float x0 = x[d] * scale, x1 = x[d + 1] * scale;
            y[d]     = x0 * cf[p] - x1 * sf[p];
            y[d + 1] = x1 * cf[p] + x0 * sf[p];
        }
        #pragma unroll
        for (int d = 0; d < 32; ++d)
            row[(d >> 3) * 8 + perm8(d & 7)] = y[d];
    }
    __syncthreads();

    // scores (3xTF32)
    {
        float c[2][2][4] = {};
        #pragma unroll
        for (int ks = 0; ks < 4; ++ks) {
            const int ko = ks * 8 + 2 * t4;
            unsigned ah[2][4], al[2][4], bh[2][2], bl[2][2];
            #pragma unroll
            for (int mt = 0; mt < 2; ++mt) {
                const int r0 = wm*32 + mt*16 + g;
                float2 xx = *(const float2*)&sq[r0    ][ko];
                float2 yy = *(const float2*)&sq[r0 + 8][ko];
                float a0 = xx.x, a2 = xx.y, a1 = yy.x, a3 = yy.y;
                ah[mt][0]=f2tf32(a0); al[mt][0]=f2tf32(a0 - __uint_as_float(ah[mt][0]));
                ah[mt][1]=f2tf32(a1); al[mt][1]=f2tf32(a1 - __uint_as_float(ah[mt][1]));
                ah[mt][2]=f2tf32(a2); al[mt][2]=f2tf32(a2 - __uint_as_float(ah[mt][2]));
                ah[mt][3]=f2tf32(a3); al[mt][3]=f2tf32(a3 - __uint_as_float(ah[mt][3]));
            }
            #pragma unroll
            for (int nt = 0; nt < 2; ++nt) {
                const int c0 = wn*16 + nt*8 + g;
                float2 bv = *(const float2*)&sk[c0][ko];
                bh[nt][0]=f2tf32(bv.x); bl[nt][0]=f2tf32(bv.x - __uint_as_float(bh[nt][0]));
                bh[nt][1]=f2tf32(bv.y); bl[nt][1]=f2tf32(bv.y - __uint_as_float(bh[nt][1]));
            }
            #pragma unroll
            for (int mt = 0; mt < 2; ++mt)
                #pragma unroll
                for (int nt = 0; nt < 2; ++nt) {
                    mma_tf32(c[mt][nt], ah[mt], bh[nt]);
                    mma_tf32(c[mt][nt], al[mt], bh[nt]);
                    mma_tf32(c[mt][nt], ah[mt], bl[nt]);
                }
        }
        const int p0 = perm8(2 * t4), p1 = perm8(2 * t4 + 1);
        #pragma unroll
        for (int mt = 0; mt < 2; ++mt) {
            const int r0 = wm*32 + mt*16 + g;
            #pragma unroll
            for (int nt = 0; nt < 2; ++nt) {
                const int cg = wn*16 + nt*8;
                sp[r0    ][cg + p0] = c[mt][nt][0];
                sp[r0    ][cg + p1] = c[mt][nt][1];
                sp[r0 + 8][cg + p0] = c[mt][nt][2];
                sp[r0 + 8][cg + p1] = c[mt][nt][3];
            }
        }
    }
    __syncthreads();

    // softmax
    {
        const int r  = t >> 2;
        const int cb = (t & 3) * 16;
        float sc[16];
        #pragma unroll
        for (int q4 = 0; q4 < 4; ++q4)
            *(float4*)&sc[q4*4] = *(const float4*)&sp[r][cb + q4*4];
        float mx = sc[0];
        #pragma unroll
        for (int i = 1; i < 16; ++i) mx = fmaxf(mx, sc[i]);
        mx = fmaxf(mx, __shfl_xor_sync(0xffffffff, mx, 1));
        mx = fmaxf(mx, __shfl_xor_sync(0xffffffff, mx, 2));
        float sum = 0.f;
        #pragma unroll
        for (int i = 0; i < 16; ++i) { sc[i] = __expf(sc[i] - mx); sum += sc[i]; }
        sum += __shfl_xor_sync(0xffffffff, sum, 1);
        sum += __shfl_xor_sync(0xffffffff, sum, 2);
        const float rinv = 1.0f / sum;
        #pragma unroll
        for (int i = 0; i < 16; ++i) sc[i] *= rinv;
        #pragma unroll
        for (int q4 = 0; q4 < 4; ++q4)
            *(float4*)&sp[r][cb + q4*4] = *(float4*)&sc[q4*4];
    }
    __syncthreads();

    // O = P V (3xTF32); store tf32-rounded in A-fragment layout for GEMM2
    {
        float c[2][4] = {};
        #pragma unroll
        for (int ks = 0; ks < 8; ++ks) {
            const int ko = ks * 8 + 2 * t4;
            unsigned ah[2][4], al[2][4], bh[2], bl[2];
            #pragma unroll
            for (int mt = 0; mt < 2; ++mt) {
                const int r0 = wm*32 + mt*16 + g;
                float2 xx = *(const float2*)&sp[r0    ][ko];
                float2 yy = *(const float2*)&sp[r0 + 8][ko];
                float a0 = xx.x, a2 = xx.y, a1 = yy.x, a3 = yy.y;
                ah[mt][0]=f2tf32(a0); al[mt][0]=f2tf32(a0 - __uint_as_float(ah[mt][0]));
                ah[mt][1]=f2tf32(a1); al[mt][1]=f2tf32(a1 - __uint_as_float(ah[mt][1]));
                ah[mt][2]=f2tf32(a2); al[mt][2]=f2tf32(a2 - __uint_as_float(ah[mt][2]));
                ah[mt][3]=f2tf32(a3); al[mt][3]=f2tf32(a3 - __uint_as_float(ah[mt][3]));
            }
            {
                const int c0 = wn*8 + g;
                float2 bv = *(const float2*)&svT[c0][ko];
                bh[0]=f2tf32(bv.x); bl[0]=f2tf32(bv.x - __uint_as_float(bh[0]));
                bh[1]=f2tf32(bv.y); bl[1]=f2tf32(bv.y - __uint_as_float(bh[1]));
            }
            #pragma unroll
            for (int mt = 0; mt < 2; ++mt) {
                mma_tf32(c[mt], ah[mt], bh);
                mma_tf32(c[mt], al[mt], bh);
                mma_tf32(c[mt], ah[mt], bl);
            }
        }
        const int col = h*HD + wn*8 + 2*t4;
        #pragma unroll
        for (int mt = 0; mt < 2; ++mt) {
            const int m0 = (int)rowm + wm*32 + mt*16 + g;
            out[a_frag_idx(m0,     col    )] = __uint_as_float(f2tf32(c[mt][0]));
            out[a_frag_idx(m0,     col + 1)] = __uint_as_float(f2tf32(c[mt][1]));
            out[a_frag_idx(m0 + 8, col    )] = __uint_as_float(f2tf32(c[mt][2]));
            out[a_frag_idx(m0 + 8, col + 1)] = __uint_as_float(f2tf32(c[mt][3]));
        }
    }
}

// ---------------------------------------------------------------------------
extern "C" void kernel_launch(void* const* d_in, const int* in_sizes, int n_in,
                              void* d_out, int out_size)
{
    const float* x           = (const float*)d_in[0];
    const float* qkv_weight  = (const float*)d_in[1];
    const float* q_bias      = (const float*)d_in[2];
    const float* v_bias      = (const float*)d_in[3];
    const float* logit_scale = (const float*)d_in[4];
    const float* proj_weight = (const float*)d_in[5];
    const float* proj_bias   = (const float*)d_in[6];
    float* outp = (float*)d_out;

    float *qkv, *att, *xc, *wqc, *wpc;
    cudaGetSymbolAddress((void**)&qkv, g_qkv);
    cudaGetSymbolAddress((void**)&att, g_att);
    cudaGetSymbolAddress((void**)&xc,  g_xc);
    cudaGetSymbolAddress((void**)&wqc, g_wqc);
    cudaGetSymbolAddress((void**)&wpc, g_wpc);

    const int smemBytes = 3 * 2 * 4096 * 4;   // 96 KB
    cudaFuncSetAttribute(mma_gemm<C3, 0>,
                         cudaFuncAttributeMaxDynamicSharedMemorySize, smemBytes);
    cudaFuncSetAttribute(mma_gemm<DIM, 1>,
                         cudaFuncAttributeMaxDynamicSharedMemorySize, smemBytes);

    // 0) RoPE tables + fragment-layout pre-pass (tf32-rounded)
    rope_init<<<1, 1024>>>();
    {
        const int nA  = MROWS / 128 * 16 * 32 * 32;
        const int nB1 = C3 / 128 * 16 * 32 * 32;
        const int nB2 = DIM / 128 * 16 * 32 * 32;
        prepA<<<(nA  + 255) / 256, 256>>>(x,           xc,  nA);
        prepB<<<(nB1 + 255) / 256, 256>>>(qkv_weight,  wqc, nB1);
        prepB<<<(nB2 + 255) / 256, 256>>>(proj_weight, wpc, nB2);
    }

    // 1) qkv = x @ Wqkv^T + [q_bias | 0 | v_bias]   (32768 x 1536 x 512)
    mma_gemm<C3, 0><<<dim3(C3/128, MROWS/128), 256, smemBytes>>>(
        xc, wqc, q_bias, v_bias, qkv);

    // 2) windowed cosine attention + RoPE (tensor cores, 3xTF32)
    attn_kernel<<<dim3(NW, HEADS, BATCH), 256>>>(logit_scale, att);

    // 3) out = att @ Wproj^T + proj_bias            (32768 x 512 x 512)
    mma_gemm<DIM, 1><<<dim3(DIM/128, MROWS/128), 256, smemBytes>>>(
        att, wpc, proj_bias, nullptr, outp);
}

// round 14
// speedup vs baseline: 1.0837x; 1.0837x over previous
#include <cuda_runtime.h>
#include <cuda_bf16.h>
#include <cstdint>

// Problem constants
#define BATCH   8
#define NW      64
#define NTOK    64
#define DIM     512
#define HEADS   16
#define HD      32
#define C3      1536
#define MROWS   (BATCH*NW*NTOK)   // 32768
#define LN100   4.605170185988092f

// Scratch (allocation-free rule: __device__ globals)
__device__ float g_qkv[(long)MROWS * C3];     // 192 MB (GEMM1 out, fp32 natural)
__device__ float g_att[(long)MROWS * DIM];    // 64 MB  (attn out, A-frag layout)
__device__ float g_xc [(long)MROWS * DIM];    // 64 MB  (x, A-frag layout)
__device__ float g_wqc[(long)C3 * DIM];       // 3 MB   (qkv W, B-frag layout)
__device__ float g_wpc[(long)DIM * DIM];      // 1 MB   (proj W, B-frag layout)
__device__ float g_ropeC[64 * 16];            // RoPE cos table [row][p]
__device__ float g_ropeS[64 * 16];            // RoPE sin table [row][p]

__device__ __forceinline__ unsigned f2tf32(float x) {
    unsigned u;
    asm("cvt.rna.tf32.f32 %0, %1;" : "=r"(u) : "f"(x));
    return u;
}
__device__ __forceinline__ void mma_tf32(float c[4], const unsigned a[4], const unsigned b[2]) {
    asm volatile(
        "mma.sync.aligned.m16n8k8.row.col.f32.tf32.tf32.f32 "
        "{%0,%1,%2,%3}, {%4,%5,%6,%7}, {%8,%9}, {%0,%1,%2,%3};"
        : "+f"(c[0]), "+f"(c[1]), "+f"(c[2]), "+f"(c[3])
        : "r"(a[0]), "r"(a[1]), "r"(a[2]), "r"(a[3]), "r"(b[0]), "r"(b[1]));
}
__device__ __forceinline__ int perm8(int kk) { return ((kk & 3) << 1) | (kk >> 2); }

__device__ __forceinline__ void cp_async16(uint32_t saddr, const void* g) {
    asm volatile("cp.async.cg.shared.global [%0], [%1], 16;" :: "r"(saddr), "l"(g));
}
__device__ __forceinline__ void cp_commit() { asm volatile("cp.async.commit_group;"); }
template<int Nw>
__device__ __forceinline__ void cp_wait() { asm volatile("cp.async.wait_group %0;" :: "n"(Nw)); }

// A-fragment layout index for element (m, k), K=512 fixed.
__device__ __forceinline__ long a_frag_idx(int m, int k) {
    const int mtile = m >> 7, mtg = (m >> 4) & 7, g = m & 7, hi = (m >> 3) & 1;
    const int ktile = k >> 5, ks = (k >> 3) & 3, t4 = k & 3, hk = (k >> 2) & 1;
    return ((long)(mtile * 16 + ktile)) * 4096 + (mtg * 4 + ks) * 128 + (g * 4 + t4) * 4 + hi + 2 * hk;
}

// ---------------------------------------------------------------------------
// RoPE table init (bitwise-identical sincosf values).
// ---------------------------------------------------------------------------
__global__ void rope_init()
{
    const int tid = threadIdx.x;            // 0..1023
    const int r = tid >> 4, p = tid & 15;
    const float inv_tab[8] = {
        1.0f, 0.31622776601683794f, 0.1f, 0.03162277660168379f,
        0.01f, 0.0031622776601683794f, 0.001f, 0.00031622776601683794f };
    const int ih = r >> 3, iw = r & 7;
    const float pos = (p < 8) ? (float)ih : (float)iw;
    const float f = pos * inv_tab[p & 7];
    float sf, cf;
    sincosf(f, &sf, &cf);
    g_ropeC[r * 16 + p] = cf;
    g_ropeS[r * 16 + p] = sf;
}

// ---------------------------------------------------------------------------
// Pre-pass A: scatter x into A-fragment layout, tf32.
// ---------------------------------------------------------------------------
__global__ __launch_bounds__(256) void prepA(
    const float* __restrict__ in, float* __restrict__ out, int nChunks)
{
    const int tid = blockIdx.x * 256 + threadIdx.x;
    if (tid >= nChunks) return;
    const int lane = tid & 31;
    const int t2   = tid >> 5;
    const int ks   = t2 & 3;
    const int mtg  = (t2 >> 2) & 7;
    const int kt   = (t2 >> 5) & 15;
    const int mt   = t2 >> 9;
    const int g = lane >> 2, t4 = lane & 3;
    const long r0 = mt * 128 + mtg * 16 + g;
    const int  k0 = kt * 32 + ks * 8 + t4;
    uint4 v;
    v.x = f2tf32(in[r0 * 512 + k0]);
    v.y = f2tf32(in[(r0 + 8) * 512 + k0]);
    v.z = f2tf32(in[r0 * 512 + k0 + 4]);
    v.w = f2tf32(in[(r0 + 8) * 512 + k0 + 4]);
    *(uint4*)(out + (long)tid * 4) = v;
}

// ---------------------------------------------------------------------------
// Pre-pass B: scatter W into B-fragment layout, tf32.
// ---------------------------------------------------------------------------
__global__ __launch_bounds__(256) void prepB(
    const float* __restrict__ in, float* __restrict__ out, int nChunks)
{
    const int tid = blockIdx.x * 256 + threadIdx.x;
    if (tid >= nChunks) return;
    const int lane = tid & 31;
    const int t2   = tid >> 5;
    const int kp   = t2 & 1;
    const int ntg  = (t2 >> 1) & 15;
    const int kt   = (t2 >> 5) & 15;
    const int nt   = t2 >> 9;
    const int g = lane >> 2, t4 = lane & 3;
    const long n  = nt * 128 + ntg * 8 + g;
    const int  k0 = kt * 32 + kp * 16 + t4;
    uint4 v;
    v.x = f2tf32(in[n * 512 + k0]);
    v.y = f2tf32(in[n * 512 + k0 + 4]);
    v.z = f2tf32(in[n * 512 + k0 + 8]);
    v.w = f2tf32(in[n * 512 + k0 + 12]);
    *(uint4*)(out + (long)tid * 4) = v;
}

// ---------------------------------------------------------------------------
// TF32 mma.sync GEMM on fragment-layout operands (R9 exact: 128 thr, 2 CTA/SM).
// ---------------------------------------------------------------------------
template<int N, int MODE>
__global__ __launch_bounds__(128, 2) void mma_gemm(
    const float* __restrict__ A, const float* __restrict__ W,
    const float* __restrict__ b0, const float* __restrict__ b1,
    float* __restrict__ C)
{
    constexpr int NT = 16;
    extern __shared__ unsigned sm[];

    const int t    = threadIdx.x;
    const int warp = t >> 5;
    const int lane = t & 31;
    const int g    = lane >> 2;
    const int t4   = lane & 3;
    const int wm   = warp >> 1;
    const int wn   = warp & 1;

    const int rowBase = blockIdx.y * 128;
    const int colBase = blockIdx.x * 128;

    const float* Abase = A + (long)blockIdx.y * 16 * 4096;
    const float* Wbase = W + (long)blockIdx.x * 16 * 4096;

    const uint32_t smBase = (uint32_t)__cvta_generic_to_shared(sm);

    auto issue = [&](int s, int i) {
        const float* Ag = Abase + (long)i * 4096;
        const float* Wg = Wbase + (long)i * 4096;
        #pragma unroll
        for (int p = 0; p < 16; ++p) {
            const int c = t + p * 128;
            const float* src = (c < 1024) ? (Ag + c * 4) : (Wg + (c - 1024) * 4);
            cp_async16(smBase + (uint32_t)(s * 8192 + c * 4) * 4u, src);
        }
        cp_commit();
    };

    float acc[4][8][4] = {};

    issue(0, 0);
    issue(1, 1);

    for (int i = 0; i < NT; ++i) {
        cp_wait<1>();
        __syncthreads();

        const unsigned* as = sm + (i % 3) * 8192;
        const unsigned* bs = as + 4096;

        #pragma unroll
        for (int kp = 0; kp < 2; ++kp) {
            uint4 bq[8];
            #pragma unroll
            for (int nt = 0; nt < 8; ++nt)
                bq[nt] = *(const uint4*)(bs + (((wn * 8 + nt) * 2 + kp) * 32 + lane) * 4);
            #pragma unroll
            for (int s2 = 0; s2 < 2; ++s2) {
                const int ks = kp * 2 + s2;
                unsigned af[4][4];
                #pragma unroll
                for (int mt = 0; mt < 4; ++mt) {
                    uint4 aq = *(const uint4*)(as + (((wm * 4 + mt) * 4 + ks) * 32 + lane) * 4);
                    af[mt][0] = aq.x; af[mt][1] = aq.y; af[mt][2] = aq.z; af[mt][3] = aq.w;
                }
                #pragma unroll
                for (int mt = 0; mt < 4; ++mt)
                    #pragma unroll
                    for (int nt = 0; nt < 8; ++nt) {
                        unsigned bf[2];
                        bf[0] = s2 ? bq[nt].z : bq[nt].x;
                        bf[1] = s2 ? bq[nt].w : bq[nt].y;
                        mma_tf32(acc[mt][nt], af[mt], bf);
                    }
            }
        }

        if (i + 2 < NT) issue((i + 2) % 3, i + 2);
        else cp_commit();
    }

    #pragma unroll
    for (int mt = 0; mt < 4; ++mt) {
        #pragma unroll
        for (int nt = 0; nt < 8; ++nt) {
            const int row0 = rowBase + wm*64 + mt*16 + g;
            const int col0 = colBase + wn*64 + nt*8 + t4*2;
            float bias0, bias1;
            if (MODE == 0) {
                bias0 = (col0 < 512) ? b0[col0] : ((col0 < 1024) ? 0.0f : b1[col0 - 1024]);
                const int c1 = col0 + 1;
                bias1 = (c1 < 512) ? b0[c1] : ((c1 < 1024) ? 0.0f : b1[c1 - 1024]);
            } else {
                bias0 = b0[col0];
                bias1 = b0[col0 + 1];
            }
            C[(long)row0 * N + col0    ] = acc[mt][nt][0] + bias0;
            C[(long)row0 * N + col0 + 1] = acc[mt][nt][1] + bias1;
            C[(long)(row0+8) * N + col0    ] = acc[mt][nt][2] + bias0;
            C[(long)(row0+8) * N + col0 + 1] = acc[mt][nt][3] + bias1;
        }
    }
}

// ---------------------------------------------------------------------------
// Per-window cosine attention with axial RoPE — tensor-core (3xTF32 = ~fp32).
// Phase 1b split across 256 threads (2 per row) to cut regs; 3 CTAs/SM.
// Output tf32-rounded in A-fragment layout for GEMM2.
// ---------------------------------------------------------------------------
__global__ __launch_bounds__(256, 3) void attn_kernel(
    const float* __restrict__ logit_scale, float* __restrict__ out)
{
    __shared__ float sq [64][40];
    __shared__ float sk [64][40];
    __shared__ float svT[32][72];
    __shared__ float sp [64][72];

    const int w = blockIdx.x, h = blockIdx.y, b = blockIdx.z;
    const int t    = threadIdx.x;
    const int warp = t >> 5;
    const int lane = t & 31;
    const int g    = lane >> 2;
    const int t4   = lane & 3;
    const int wm   = warp >> 2;
    const int wn   = warp & 3;

    const long rowm = (long)(b * NW + w) * NTOK;
    const float* qp = g_qkv + rowm * C3 + h * HD;
    const float* kp = qp + 512;
    const float* vp = qp + 1024;

    #pragma unroll
    for (int it = 0; it < 2; ++it) {
        int idx = t + it * 256;
        int r = idx >> 3, c = (idx & 7) * 4;
        *(float4*)&sq[r][c] = *(const float4*)(qp + (long)r * C3 + c);
        *(float4*)&sk[r][c] = *(const float4*)(kp + (long)r * C3 + c);
    }
    {
        const int r  = t & 63;
        const int pr = (r >> 3) * 8 + perm8(r & 7);
        #pragma unroll
        for (int it = 0; it < 2; ++it) {
            int c = ((t >> 6) * 2 + it) * 4;
            float4 v = *(const float4*)(vp + (long)r * C3 + c);
            svT[c+0][pr] = v.x; svT[c+1][pr] = v.y;
            svT[c+2][pr] = v.z; svT[c+3][pr] = v.w;
        }
    }
    __syncthreads();

    // ---- Phase 1b: 2 threads per row; full-row ss (bitwise order), half RoPE
    {
        const int isK  = t >> 7;            // 0: q rows, 1: k rows
        const int r    = (t >> 1) & 63;
        const int half = t & 1;             // elems [half*16, half*16+16)
        float* row = isK ? &sk[r][0] : &sq[r][0];

        // full-row sum of squares in original scalar order
        float ss = 0.f;
        #pragma unroll
        for (int c4 = 0; c4 < 8; ++c4) {
            float4 v = *(const float4*)&row[c4*4];
            ss += v.x * v.x; ss += v.y * v.y; ss += v.z * v.z; ss += v.w * v.w;
        }
        float scale = 1.0f / fmaxf(sqrtf(ss), 1e-12f);
        if (!isK)
            scale *= expf(fmaxf(logit_scale[h], LN100)) * 0.17677669529663687f;

        // own 16 elements + rope table halves
        float x[16];
        #pragma unroll
        for (int c4 = 0; c4 < 4; ++c4)
            *(float4*)&x[c4*4] = *(const float4*)&row[half*16 + c4*4];
        float cf[8], sf[8];
        *(float4*)&cf[0] = *(const float4*)&g_ropeC[r*16 + half*8];
        *(float4*)&cf[4] = *(const float4*)&g_ropeC[r*16 + half*8 + 4];
        *(float4*)&sf[0] = *(const float4*)&g_ropeS[r*16 + half*8];
        *(float4*)&sf[4] = *(const float4*)&g_ropeS[r*16 + half*8 + 4];

        float y[16];
        #pragma unroll
        for (int p = 0; p < 8; ++p) {
            const int d = 2 * p;
            const float x0 = x[d] * scale, x1 = x[d + 1] * scale;
            y[d]     = x0 * cf[p] - x1 * sf[p];
            y[d + 1] = x1 * cf[p] + x0 * sf[p];
        }

        __syncwarp();   // both halves of each row finished reading

        #pragma unroll
        for (int d = 0; d < 16; ++d) {
            const int dd = half * 16 + d;
            row[(dd >> 3) * 8 + perm8(dd & 7)] = y[d];
        }
    }
    __syncthreads();

    // scores (3xTF32)
    {
        float c[2][2][4] = {};
        #pragma unroll
        for (int ks = 0; ks < 4; ++ks) {
            const int ko = ks * 8 + 2 * t4;
            unsigned ah[2][4], al[2][4], bh[2][2], bl[2][2];
            #pragma unroll
            for (int mt = 0; mt < 2; ++mt) {
                const int r0 = wm*32 + mt*16 + g;
                float2 xx = *(const float2*)&sq[r0    ][ko];
                float2 yy = *(const float2*)&sq[r0 + 8][ko];
                float a0 = xx.x, a2 = xx.y, a1 = yy.x, a3 = yy.y;
                ah[mt][0]=f2tf32(a0); al[mt][0]=f2tf32(a0 - __uint_as_float(ah[mt][0]));
                ah[mt][1]=f2tf32(a1); al[mt][1]=f2tf32(a1 - __uint_as_float(ah[mt][1]));
                ah[mt][2]=f2tf32(a2); al[mt][2]=f2tf32(a2 - __uint_as_float(ah[mt][2]));
                ah[mt][3]=f2tf32(a3); al[mt][3]=f2tf32(a3 - __uint_as_float(ah[mt][3]));
            }
            #pragma unroll
            for (int nt = 0; nt < 2; ++nt) {
                const int c0 = wn*16 + nt*8 + g;
                float2 bv = *(const float2*)&sk[c0][ko];
                bh[nt][0]=f2tf32(bv.x); bl[nt][0]=f2tf32(bv.x - __uint_as_float(bh[nt][0]));
                bh[nt][1]=f2tf32(bv.y); bl[nt][1]=f2tf32(bv.y - __uint_as_float(bh[nt][1]));
            }
            #pragma unroll
            for (int mt = 0; mt < 2; ++mt)
                #pragma unroll
                for (int nt = 0; nt < 2; ++nt) {
                    mma_tf32(c[mt][nt], ah[mt], bh[nt]);
                    mma_tf32(c[mt][nt], al[mt], bh[nt]);
                    mma_tf32(c[mt][nt], ah[mt], bl[nt]);
                }
        }
        const int p0 = perm8(2 * t4), p1 = perm8(2 * t4 + 1);
        #pragma unroll
        for (int mt = 0; mt < 2; ++mt) {
            const int r0 = wm*32 + mt*16 + g;
            #pragma unroll
            for (int nt = 0; nt < 2; ++nt) {
                const int cg = wn*16 + nt*8;
                sp[r0    ][cg + p0] = c[mt][nt][0];
                sp[r0    ][cg + p1] = c[mt][nt][1];
                sp[r0 + 8][cg + p0] = c[mt][nt][2];
                sp[r0 + 8][cg + p1] = c[mt][nt][3];
            }
        }
    }
    __syncthreads();

    // softmax
    {
        const int r  = t >> 2;
        const int cb = (t & 3) * 16;
        float sc[16];
        #pragma unroll
        for (int q4 = 0; q4 < 4; ++q4)
            *(float4*)&sc[q4*4] = *(const float4*)&sp[r][cb + q4*4];
        float mx = sc[0];
        #pragma unroll
        for (int i = 1; i < 16; ++i) mx = fmaxf(mx, sc[i]);
        mx = fmaxf(mx, __shfl_xor_sync(0xffffffff, mx, 1));
        mx = fmaxf(mx, __shfl_xor_sync(0xffffffff, mx, 2));
        float sum = 0.f;
        #pragma unroll
        for (int i = 0; i < 16; ++i) { sc[i] = __expf(sc[i] - mx); sum += sc[i]; }
        sum += __shfl_xor_sync(0xffffffff, sum, 1);
        sum += __shfl_xor_sync(0xffffffff, sum, 2);
        const float rinv = 1.0f / sum;
        #pragma unroll
        for (int i = 0; i < 16; ++i) sc[i] *= rinv;
        #pragma unroll
        for (int q4 = 0; q4 < 4; ++q4)
            *(float4*)&sp[r][cb + q4*4] = *(float4*)&sc[q4*4];
    }
    __syncthreads();

    // O = P V (3xTF32); store tf32-rounded in A-fragment layout for GEMM2
    {
        float c[2][4] = {};
        #pragma unroll
        for (int ks = 0; ks < 8; ++ks) {
            const int ko = ks * 8 + 2 * t4;
            unsigned ah[2][4], al[2][4], bh[2], bl[2];
            #pragma unroll
            for (int mt = 0; mt < 2; ++mt) {
                const int r0 = wm*32 + mt*16 + g;
                float2 xx = *(const float2*)&sp[r0    ][ko];
                float2 yy = *(const float2*)&sp[r0 + 8][ko];
                float a0 = xx.x, a2 = xx.y, a1 = yy.x, a3 = yy.y;
                ah[mt][0]=f2tf32(a0); al[mt][0]=f2tf32(a0 - __uint_as_float(ah[mt][0]));
                ah[mt][1]=f2tf32(a1); al[mt][1]=f2tf32(a1 - __uint_as_float(ah[mt][1]));
                ah[mt][2]=f2tf32(a2); al[mt][2]=f2tf32(a2 - __uint_as_float(ah[mt][2]));
                ah[mt][3]=f2tf32(a3); al[mt][3]=f2tf32(a3 - __uint_as_float(ah[mt][3]));
            }
            {
                const int c0 = wn*8 + g;
                float2 bv = *(const float2*)&svT[c0][ko];
                bh[0]=f2tf32(bv.x); bl[0]=f2tf32(bv.x - __uint_as_float(bh[0]));
                bh[1]=f2tf32(bv.y); bl[1]=f2tf32(bv.y - __uint_as_float(bh[1]));
            }
            #pragma unroll
            for (int mt = 0; mt < 2; ++mt) {
                mma_tf32(c[mt], ah[mt], bh);
                mma_tf32(c[mt], al[mt], bh);
                mma_tf32(c[mt], ah[mt], bl);
            }
        }
        const int col = h*HD + wn*8 + 2*t4;
        #pragma unroll
        for (int mt = 0; mt < 2; ++mt) {
            const int m0 = (int)rowm + wm*32 + mt*16 + g;
            out[a_frag_idx(m0,     col    )] = __uint_as_float(f2tf32(c[mt][0]));
            out[a_frag_idx(m0,     col + 1)] = __uint_as_float(f2tf32(c[mt][1]));
            out[a_frag_idx(m0 + 8, col    )] = __uint_as_float(f2tf32(c[mt][2]));
            out[a_frag_idx(m0 + 8, col + 1)] = __uint_as_float(f2tf32(c[mt][3]));
        }
    }
}

// ---------------------------------------------------------------------------
extern "C" void kernel_launch(void* const* d_in, const int* in_sizes, int n_in,
                              void* d_out, int out_size)
{
    const float* x           = (const float*)d_in[0];
    const float* qkv_weight  = (const float*)d_in[1];
    const float* q_bias      = (const float*)d_in[2];
    const float* v_bias      = (const float*)d_in[3];
    const float* logit_scale = (const float*)d_in[4];
    const float* proj_weight = (const float*)d_in[5];
    const float* proj_bias   = (const float*)d_in[6];
    float* outp = (float*)d_out;

    float *qkv, *att, *xc, *wqc, *wpc;
    cudaGetSymbolAddress((void**)&qkv, g_qkv);
    cudaGetSymbolAddress((void**)&att, g_att);
    cudaGetSymbolAddress((void**)&xc,  g_xc);
    cudaGetSymbolAddress((void**)&wqc, g_wqc);
    cudaGetSymbolAddress((void**)&wpc, g_wpc);

    const int smemBytes = 3 * 2 * 4096 * 4;   // 96 KB
    cudaFuncSetAttribute(mma_gemm<C3, 0>,
                         cudaFuncAttributeMaxDynamicSharedMemorySize, smemBytes);
    cudaFuncSetAttribute(mma_gemm<DIM, 1>,
                         cudaFuncAttributeMaxDynamicSharedMemorySize, smemBytes);

    // 0) RoPE tables + fragment-layout pre-pass (tf32-rounded)
    rope_init<<<1, 1024>>>();
    {
        const int nA  = MROWS / 128 * 16 * 32 * 32;
        const int nB1 = C3 / 128 * 16 * 32 * 32;
        const int nB2 = DIM / 128 * 16 * 32 * 32;
        prepA<<<(nA  + 255) / 256, 256>>>(x,           xc,  nA);
        prepB<<<(nB1 + 255) / 256, 256>>>(qkv_weight,  wqc, nB1);
        prepB<<<(nB2 + 255) / 256, 256>>>(proj_weight, wpc, nB2);
    }

    // 1) qkv = x @ Wqkv^T + [q_bias | 0 | v_bias]   (32768 x 1536 x 512)
    mma_gemm<C3, 0><<<dim3(C3/128, MROWS/128), 128, smemBytes>>>(
        xc, wqc, q_bias, v_bias, qkv);

    // 2) windowed cosine attention + RoPE (tensor cores, 3xTF32)
    attn_kernel<<<dim3(NW, HEADS, BATCH), 256>>>(logit_scale, att);

    // 3) out = att @ Wproj^T + proj_bias            (32768 x 512 x 512)
    mma_gemm<DIM, 1><<<dim3(DIM/128, MROWS/128), 128, smemBytes>>>(
        att, wpc, proj_bias, nullptr, outp);
}